// round 6
// baseline (speedup 1.0000x reference)
#include <cuda_runtime.h>
#include <cuda_bf16.h>
#include <math_constants.h>
#include <cstdint>

// Problem dims (fixed): B=64, T=512, D=256, C=1024, H=1
#define N_TOK 32768
#define DIM   256
#define NCODE 1024

#define DECAY 0.99f
#define ONE_M_DECAY 0.01f
#define EPS 1e-5f

// Output packing (tuple flattened, all float32):
#define OFF_Q    0
#define OFF_IND  8388608
#define OFF_NORM 8421376
#define OFF_CS   8683520

#define NCHUNK 16   // code chunks of 64

// ---------------- scratch (no cudaMalloc allowed) ----------------
__device__ float g_counts[NCODE];
__device__ float g_esum[NCODE * DIM];
__device__ float g_enorm[NCODE];
__device__ float g_inv[NCODE];
__device__ int   g_idx[N_TOK];
__device__ float g_pbest[NCHUNK * N_TOK];
__device__ int   g_pidx[NCHUNK * N_TOK];
// precomputed bf16 hi/lo splits
__device__ __align__(256) __nv_bfloat16 g_xh[N_TOK * DIM];
__device__ __align__(256) __nv_bfloat16 g_xl[N_TOK * DIM];
__device__ __align__(256) __nv_bfloat16 g_eh[NCODE * DIM];
__device__ __align__(256) __nv_bfloat16 g_el[NCODE * DIM];

// ---------------- mma / cp.async helpers (baseline PTX, sm_80+) ----------------
__device__ __forceinline__ void ldsm_x4(uint32_t* r, uint32_t addr) {
    asm volatile("ldmatrix.sync.aligned.m8n8.x4.shared.b16 {%0,%1,%2,%3}, [%4];"
        : "=r"(r[0]), "=r"(r[1]), "=r"(r[2]), "=r"(r[3]) : "r"(addr));
}
__device__ __forceinline__ void mma_bf16(float* d, const uint32_t* a, const uint32_t* b) {
    asm volatile("mma.sync.aligned.m16n8k16.row.col.f32.bf16.bf16.f32 "
        "{%0,%1,%2,%3}, {%4,%5,%6,%7}, {%8,%9}, {%0,%1,%2,%3};"
        : "+f"(d[0]), "+f"(d[1]), "+f"(d[2]), "+f"(d[3])
        : "r"(a[0]), "r"(a[1]), "r"(a[2]), "r"(a[3]), "r"(b[0]), "r"(b[1]));
}
#define CP_ASYNC16(dst, src) \
    asm volatile("cp.async.cg.shared.global [%0], [%1], 16;" :: "r"(dst), "l"(src))
#define CP_COMMIT() asm volatile("cp.async.commit_group;")
#define CP_WAIT(n)  asm volatile("cp.async.wait_group %0;" :: "n"(n))

__device__ __forceinline__ void bsplit(float v, unsigned short& h, unsigned short& l) {
    __nv_bfloat16 hb = __float2bfloat16(v);
    h = __bfloat16_as_ushort(hb);
    l = __bfloat16_as_ushort(__float2bfloat16(v - __bfloat162float(hb)));
}

// ---------------- kernel 0: precompute bf16 hi/lo splits ----------------
// blocks 0..8191: x (float4 per thread). blocks 8192..8447: embed.
__global__ void k_prep(const float* __restrict__ x, const float* __restrict__ embed) {
    int gid = blockIdx.x * 256 + threadIdx.x;
    const float4* src;
    uint2* dh;
    uint2* dl;
    int e;
    if (blockIdx.x < 8192) {
        src = (const float4*)x; e = gid;
        dh = (uint2*)g_xh; dl = (uint2*)g_xl;
    } else {
        src = (const float4*)embed; e = gid - 8192 * 256;
        dh = (uint2*)g_eh; dl = (uint2*)g_el;
    }
    float4 v = src[e];
    unsigned short h0, l0, h1, l1, h2, l2, h3, l3;
    bsplit(v.x, h0, l0);
    bsplit(v.y, h1, l1);
    bsplit(v.z, h2, l2);
    bsplit(v.w, h3, l3);
    dh[e] = make_uint2((uint32_t)h0 | ((uint32_t)h1 << 16),
                       (uint32_t)h2 | ((uint32_t)h3 << 16));
    dl[e] = make_uint2((uint32_t)l0 | ((uint32_t)l1 << 16),
                       (uint32_t)l2 | ((uint32_t)l3 << 16));
}

// ---------------- kernel 1: ||e_c||^2 ----------------
__global__ void k_enorm(const float* __restrict__ embed) {
    int w = threadIdx.x >> 5;
    int l = threadIdx.x & 31;
    int code = blockIdx.x * 4 + w;
    const float* row = embed + (size_t)code * DIM;
    float s = 0.0f;
#pragma unroll
    for (int i = 0; i < 8; ++i) {
        float v = row[l + 32 * i];
        s = fmaf(v, v, s);
    }
#pragma unroll
    for (int off = 16; off > 0; off >>= 1)
        s += __shfl_down_sync(0xffffffffu, s, off);
    if (l == 0) g_enorm[code] = s;
}

// ---------------- kernel 2: bf16x3 mma.sync GEMM + partial argmax ----------------
// grid (256, 16): x = 128-token tile, y = 64-code chunk. 256 threads = 8 warps.
// Warp tile 32 tok x 32 codes. K=256 in 4 double-buffered kc=64 stages, cp.async.
#define ROWB 144
#define SA_HI 0
#define SA_LO 18432
#define SB_HI 36864
#define SB_LO 46080
#define BUFB  55296
#define DSMEM2 (2 * BUFB)

__device__ __forceinline__ void load_stage(uint32_t sb, int b, int s, int tid,
                                           int blockTok, int code0) {
    const char* xh = (const char*)__cvta_generic_to_global(g_xh);
    const char* xl = (const char*)__cvta_generic_to_global(g_xl);
    const char* eh = (const char*)__cvta_generic_to_global(g_eh);
    const char* el = (const char*)__cvta_generic_to_global(g_el);
    const uint32_t buf = sb + b * BUFB;
    const int kb = s * 128;  // byte offset of kc=64 bf16 chunk within a 512B row
#pragma unroll
    for (int i = 0; i < 4; ++i) {
        int c = tid + i * 256;       // 0..1023
        int row = c >> 3, cb = c & 7;
        size_t so = (size_t)(blockTok + row) * 512 + kb + cb * 16;
        uint32_t dof = row * ROWB + cb * 16;
        CP_ASYNC16(buf + SA_HI + dof, xh + so);
        CP_ASYNC16(buf + SA_LO + dof, xl + so);
    }
#pragma unroll
    for (int i = 0; i < 2; ++i) {
        int c = tid + i * 256;       // 0..511
        int row = c >> 3, cb = c & 7;
        size_t so = (size_t)(code0 + row) * 512 + kb + cb * 16;
        uint32_t dof = row * ROWB + cb * 16;
        CP_ASYNC16(buf + SB_HI + dof, eh + so);
        CP_ASYNC16(buf + SB_LO + dof, el + so);
    }
}

__global__ void __launch_bounds__(256, 2)
k_gemm_mma(const float* __restrict__ x, const float* __restrict__ embed) {
    extern __shared__ char smem[];
    uint32_t sb;
    asm("{ .reg .u64 t; cvta.to.shared.u64 t, %1; cvt.u32.u64 %0, t; }"
        : "=r"(sb) : "l"(smem));

    const int tid = threadIdx.x;
    const int wid = tid >> 5;
    const int lane = tid & 31;
    const int wm = wid & 3;      // token strip (32)
    const int wn = wid >> 2;     // code strip (32)
    const int blockTok = blockIdx.x * 128;
    const int cc = blockIdx.y;
    const int code0 = cc * 64;

    float acc[2][4][4];
#pragma unroll
    for (int t = 0; t < 2; ++t)
#pragma unroll
        for (int j = 0; j < 4; ++j)
#pragma unroll
            for (int r = 0; r < 4; ++r) acc[t][j][r] = 0.0f;

    const uint32_t arow = (uint32_t)((wm * 32 + (lane & 15)) * ROWB + (lane >> 4) * 16);
    const int g8 = lane >> 3;
    const uint32_t brow = (uint32_t)((wn * 32 + (g8 >> 1) * 8 + (lane & 7)) * ROWB
                                     + (g8 & 1) * 16);

    load_stage(sb, 0, 0, tid, blockTok, code0);
    CP_COMMIT();

    for (int s = 0; s < 4; ++s) {
        const int b = s & 1;
        if (s < 3) {
            load_stage(sb, b ^ 1, s + 1, tid, blockTok, code0);
            CP_COMMIT();
            CP_WAIT(1);
        } else {
            CP_WAIT(0);
        }
        __syncthreads();

        const uint32_t base = sb + b * BUFB;
#pragma unroll
        for (int ks = 0; ks < 4; ++ks) {
            const uint32_t k0 = ks * 32;
            uint32_t ah[2][4], al[2][4], bh[4][2], bl[4][2];
#pragma unroll
            for (int jj = 0; jj < 2; ++jj) {
                uint32_t r[4];
                ldsm_x4(r, base + SB_HI + brow + jj * 16 * ROWB + k0);
                bh[2 * jj][0] = r[0]; bh[2 * jj][1] = r[1];
                bh[2 * jj + 1][0] = r[2]; bh[2 * jj + 1][1] = r[3];
                ldsm_x4(r, base + SB_LO + brow + jj * 16 * ROWB + k0);
                bl[2 * jj][0] = r[0]; bl[2 * jj][1] = r[1];
                bl[2 * jj + 1][0] = r[2]; bl[2 * jj + 1][1] = r[3];
            }
#pragma unroll
            for (int t = 0; t < 2; ++t) {
                ldsm_x4(ah[t], base + SA_HI + arow + t * 16 * ROWB + k0);
                ldsm_x4(al[t], base + SA_LO + arow + t * 16 * ROWB + k0);
            }
#pragma unroll
            for (int t = 0; t < 2; ++t)
#pragma unroll
                for (int j = 0; j < 4; ++j) {
                    mma_bf16(acc[t][j], ah[t], bh[j]);
                    mma_bf16(acc[t][j], ah[t], bl[j]);
                    mma_bf16(acc[t][j], al[t], bh[j]);
                }
        }
        __syncthreads();
    }

    // ---- epilogue: score + argmax ----
    const int g = lane >> 2;       // row within 8
    const int tg = lane & 3;       // col pair selector
    float best[4];
    int bidx[4];
#pragma unroll
    for (int r = 0; r < 4; ++r) { best[r] = -CUDART_INF_F; bidx[r] = 0x7fffffff; }

#pragma unroll
    for (int t = 0; t < 2; ++t) {
#pragma unroll
        for (int j = 0; j < 4; ++j) {
            int c0 = code0 + wn * 32 + j * 8 + tg * 2;
            float e0 = __ldg(&g_enorm[c0]);
            float e1 = __ldg(&g_enorm[c0 + 1]);
            float s00 = fmaf(2.0f, acc[t][j][0], -e0);
            float s01 = fmaf(2.0f, acc[t][j][1], -e1);
            float s10 = fmaf(2.0f, acc[t][j][2], -e0);
            float s11 = fmaf(2.0f, acc[t][j][3], -e1);
            int r0 = t * 2, r1 = t * 2 + 1;
            if (s00 > best[r0]) { best[r0] = s00; bidx[r0] = c0; }
            if (s01 > best[r0]) { best[r0] = s01; bidx[r0] = c0 + 1; }
            if (s10 > best[r1]) { best[r1] = s10; bidx[r1] = c0; }
            if (s11 > best[r1]) { best[r1] = s11; bidx[r1] = c0 + 1; }
        }
    }
#pragma unroll
    for (int r = 0; r < 4; ++r) {
#pragma unroll
        for (int off = 1; off < 4; off <<= 1) {
            float os = __shfl_xor_sync(0xffffffffu, best[r], off);
            int   oi = __shfl_xor_sync(0xffffffffu, bidx[r], off);
            if (os > best[r] || (os == best[r] && oi < bidx[r])) { best[r] = os; bidx[r] = oi; }
        }
    }

    __syncthreads();  // buffers done; reuse smem as reduce scratch
    float* red_s = (float*)smem;               // [128][2]
    int*   red_i = (int*)(smem + 1024);        // [128][2]
    if (tg == 0) {
#pragma unroll
        for (int r = 0; r < 4; ++r) {
            int t = r >> 1, rh = r & 1;
            int lrow = wm * 32 + t * 16 + rh * 8 + g;
            red_s[lrow * 2 + wn] = best[r];
            red_i[lrow * 2 + wn] = bidx[r];
        }
    }
    __syncthreads();
    if (tid < 128) {
        float s0 = red_s[tid * 2], s1 = red_s[tid * 2 + 1];
        int i0 = red_i[tid * 2], i1 = red_i[tid * 2 + 1];
        float bs = s0; int bb = i0;
        if (s1 > s0) { bs = s1; bb = i1; }   // strip 0 has lower codes: tie keeps 0
        int tok = blockTok + tid;
        g_pbest[cc * N_TOK + tok] = bs;
        g_pidx[cc * N_TOK + tok] = bb;
    }
}

// ---------------- kernel 3: cross-chunk argmax reduce ----------------
__global__ void k_argmax_reduce(float* __restrict__ out_ind) {
    int tok = blockIdx.x * 256 + threadIdx.x;
    float bs = -CUDART_INF_F;
    int bi = 0x7fffffff;
#pragma unroll
    for (int cc = 0; cc < NCHUNK; ++cc) {
        float s = g_pbest[cc * N_TOK + tok];
        int i = g_pidx[cc * N_TOK + tok];
        if (s > bs) { bs = s; bi = i; }  // ascending chunks: strict > keeps lowest idx
    }
    g_idx[tok] = bi;
    out_ind[tok] = (float)bi;
}

// ---------------- kernel 4: gather quantize ----------------
__global__ void k_quant(const float* __restrict__ embed,
                        float* __restrict__ out_q) {
    int token = blockIdx.x * 8 + (threadIdx.x >> 5);
    int lane = threadIdx.x & 31;
    int idx = g_idx[token];
    const float4* er = (const float4*)(embed + (size_t)idx * DIM);
    float4* qw = (float4*)(out_q + (size_t)token * DIM);
    qw[lane] = er[lane];
    qw[lane + 32] = er[lane + 32];
}

// ---------------- kernel 5: per-code deterministic accumulation ----------------
__global__ __launch_bounds__(256)
void k_accum(const float* __restrict__ x) {
    const int c = blockIdx.x;
    const int tid = threadIdx.x;
    const int lane = tid & 31;
    const int w = tid >> 5;

    __shared__ int list[256];
    __shared__ int wcnt[8];
    __shared__ int wbase[8];
    __shared__ int s_n;

    float acc = 0.0f;
    int total = 0;

    for (int base = 0; base < N_TOK; base += 256) {
        int t = base + tid;
        bool m = (g_idx[t] == c);
        unsigned ball = __ballot_sync(0xffffffffu, m);
        if (lane == 0) wcnt[w] = __popc(ball);
        __syncthreads();
        if (tid == 0) {
            int s = 0;
#pragma unroll
            for (int i = 0; i < 8; ++i) { wbase[i] = s; s += wcnt[i]; }
            s_n = s;
        }
        __syncthreads();
        if (m) {
            int r = __popc(ball & ((1u << lane) - 1u));
            list[wbase[w] + r] = t;
        }
        __syncthreads();
        int n = s_n;
        for (int j = 0; j < n; ++j)
            acc += x[(size_t)list[j] * DIM + tid];
        total += n;
        __syncthreads();
    }

    g_esum[(size_t)c * DIM + tid] = acc;
    if (tid == 0) g_counts[c] = (float)total;
}

// ---------------- kernel 6a: cs_new + Laplace smoothing reciprocal ----------------
__global__ void k_finA(const float* __restrict__ cluster_size,
                       float* __restrict__ out_cs) {
    __shared__ float red[NCODE];
    int c = threadIdx.x;
    float csn = DECAY * cluster_size[c] + ONE_M_DECAY * g_counts[c];
    out_cs[c] = csn;
    red[c] = csn;
    __syncthreads();
#pragma unroll
    for (int s = 512; s > 0; s >>= 1) {
        if (c < s) red[c] += red[c + s];
        __syncthreads();
    }
    float n = red[0];
    float denom = (csn + EPS) / (n + (float)NCODE * EPS) * n;
    g_inv[c] = 1.0f / denom;
}

// ---------------- kernel 6b: embed_norm ----------------
__global__ void k_finB(const float* __restrict__ embed_avg,
                       float* __restrict__ out_norm) {
    int i = blockIdx.x * blockDim.x + threadIdx.x;
    if (i < NCODE * DIM) {
        float ea = DECAY * embed_avg[i] + ONE_M_DECAY * g_esum[i];
        out_norm[i] = ea * g_inv[i >> 8];
    }
}

// ---------------- launch ----------------
extern "C" void kernel_launch(void* const* d_in, const int* in_sizes, int n_in,
                              void* d_out, int out_size) {
    const float* x = (const float*)d_in[0];
    const float* embed = (const float*)d_in[1];
    const float* embed_avg = (const float*)d_in[2];
    const float* cluster_size = (const float*)d_in[3];
    float* out = (float*)d_out;

    float* out_q    = out + OFF_Q;
    float* out_ind  = out + OFF_IND;
    float* out_norm = out + OFF_NORM;
    float* out_cs   = out + OFF_CS;

    cudaFuncSetAttribute(k_gemm_mma,
                         cudaFuncAttributeMaxDynamicSharedMemorySize,
                         DSMEM2);

    k_prep<<<8448, 256>>>(x, embed);
    k_enorm<<<NCODE / 4, 128>>>(embed);
    dim3 g(N_TOK / 128, NCHUNK);
    k_gemm_mma<<<g, 256, DSMEM2>>>(x, embed);
    k_argmax_reduce<<<N_TOK / 256, 256>>>(out_ind);
    k_quant<<<N_TOK / 8, 256>>>(embed, out_q);
    k_accum<<<NCODE, 256>>>(x);
    k_finA<<<1, NCODE>>>(cluster_size, out_cs);
    k_finB<<<(NCODE * DIM + 255) / 256, 256>>>(embed_avg, out_norm);
}

// round 7
// speedup vs baseline: 1.0250x; 1.0250x over previous
#include <cuda_runtime.h>
#include <cuda_bf16.h>
#include <math_constants.h>
#include <cstdint>

// Problem dims (fixed): B=64, T=512, D=256, C=1024, H=1
#define N_TOK 32768
#define DIM   256
#define NCODE 1024

#define DECAY 0.99f
#define ONE_M_DECAY 0.01f
#define EPS 1e-5f

// Output packing (tuple flattened, all float32):
#define OFF_Q    0
#define OFF_IND  8388608
#define OFF_NORM 8421376
#define OFF_CS   8683520

#define NCHUNK 8   // code chunks of 128

// ---------------- scratch (no cudaMalloc allowed) ----------------
__device__ float g_counts[NCODE];
__device__ float g_esum[NCODE * DIM];
__device__ float g_enorm[NCODE];
__device__ float g_inv[NCODE];
__device__ int   g_idx[N_TOK];
__device__ float g_pbest[NCHUNK * N_TOK];
__device__ int   g_pidx[NCHUNK * N_TOK];
// precomputed bf16 hi/lo splits
__device__ __align__(256) __nv_bfloat16 g_xh[N_TOK * DIM];
__device__ __align__(256) __nv_bfloat16 g_xl[N_TOK * DIM];
__device__ __align__(256) __nv_bfloat16 g_eh[NCODE * DIM];
__device__ __align__(256) __nv_bfloat16 g_el[NCODE * DIM];

// ---------------- mma / cp.async helpers (baseline PTX, sm_80+) ----------------
__device__ __forceinline__ void ldsm_x4(uint32_t* r, uint32_t addr) {
    asm volatile("ldmatrix.sync.aligned.m8n8.x4.shared.b16 {%0,%1,%2,%3}, [%4];"
        : "=r"(r[0]), "=r"(r[1]), "=r"(r[2]), "=r"(r[3]) : "r"(addr));
}
__device__ __forceinline__ void mma_bf16(float* d, const uint32_t* a, const uint32_t* b) {
    asm volatile("mma.sync.aligned.m16n8k16.row.col.f32.bf16.bf16.f32 "
        "{%0,%1,%2,%3}, {%4,%5,%6,%7}, {%8,%9}, {%0,%1,%2,%3};"
        : "+f"(d[0]), "+f"(d[1]), "+f"(d[2]), "+f"(d[3])
        : "r"(a[0]), "r"(a[1]), "r"(a[2]), "r"(a[3]), "r"(b[0]), "r"(b[1]));
}
#define CP_ASYNC16(dst, src) \
    asm volatile("cp.async.cg.shared.global [%0], [%1], 16;" :: "r"(dst), "l"(src))
#define CP_COMMIT() asm volatile("cp.async.commit_group;")
#define CP_WAIT(n)  asm volatile("cp.async.wait_group %0;" :: "n"(n))

__device__ __forceinline__ void bsplit(float v, unsigned short& h, unsigned short& l) {
    __nv_bfloat16 hb = __float2bfloat16(v);
    h = __bfloat16_as_ushort(hb);
    l = __bfloat16_as_ushort(__float2bfloat16(v - __bfloat162float(hb)));
}

// ---------------- kernel 0: precompute bf16 hi/lo splits ----------------
__global__ void k_prep(const float* __restrict__ x, const float* __restrict__ embed) {
    int gid = blockIdx.x * 256 + threadIdx.x;
    const float4* src;
    uint2* dh;
    uint2* dl;
    int e;
    if (blockIdx.x < 8192) {
        src = (const float4*)x; e = gid;
        dh = (uint2*)g_xh; dl = (uint2*)g_xl;
    } else {
        src = (const float4*)embed; e = gid - 8192 * 256;
        dh = (uint2*)g_eh; dl = (uint2*)g_el;
    }
    float4 v = src[e];
    unsigned short h0, l0, h1, l1, h2, l2, h3, l3;
    bsplit(v.x, h0, l0);
    bsplit(v.y, h1, l1);
    bsplit(v.z, h2, l2);
    bsplit(v.w, h3, l3);
    dh[e] = make_uint2((uint32_t)h0 | ((uint32_t)h1 << 16),
                       (uint32_t)h2 | ((uint32_t)h3 << 16));
    dl[e] = make_uint2((uint32_t)l0 | ((uint32_t)l1 << 16),
                       (uint32_t)l2 | ((uint32_t)l3 << 16));
}

// ---------------- kernel 1: ||e_c||^2 ----------------
__global__ void k_enorm(const float* __restrict__ embed) {
    int w = threadIdx.x >> 5;
    int l = threadIdx.x & 31;
    int code = blockIdx.x * 4 + w;
    const float* row = embed + (size_t)code * DIM;
    float s = 0.0f;
#pragma unroll
    for (int i = 0; i < 8; ++i) {
        float v = row[l + 32 * i];
        s = fmaf(v, v, s);
    }
#pragma unroll
    for (int off = 16; off > 0; off >>= 1)
        s += __shfl_down_sync(0xffffffffu, s, off);
    if (l == 0) g_enorm[code] = s;
}

// ---------------- kernel 2: bf16x3 mma.sync GEMM + partial argmax ----------------
// grid (256, 8): x = 128-token tile, y = 128-code chunk. 256 threads = 8 warps.
// Warp tile 32 tok x 64 codes. K=256 in 8 double-buffered kc=32 stages (cp.async).
#define ROWB 80
#define SA_HI 0
#define SA_LO 10240
#define SB_HI 20480
#define SB_LO 30720
#define BUFB  40960
#define DSMEM2 (2 * BUFB)

__device__ __forceinline__ void load_stage(uint32_t sb, int b, int s, int tid,
                                           int blockTok, int code0) {
    const char* xh = (const char*)__cvta_generic_to_global(g_xh);
    const char* xl = (const char*)__cvta_generic_to_global(g_xl);
    const char* eh = (const char*)__cvta_generic_to_global(g_eh);
    const char* el = (const char*)__cvta_generic_to_global(g_el);
    const uint32_t buf = sb + b * BUFB;
    const int kb = s * 64;  // byte offset of kc=32 bf16 chunk within a 512B row
#pragma unroll
    for (int i = 0; i < 2; ++i) {
        int c = tid + i * 256;       // 0..511
        int row = c >> 2, cb = c & 3;
        size_t so = (size_t)(blockTok + row) * 512 + kb + cb * 16;
        uint32_t dof = row * ROWB + cb * 16;
        CP_ASYNC16(buf + SA_HI + dof, xh + so);
        CP_ASYNC16(buf + SA_LO + dof, xl + so);
    }
#pragma unroll
    for (int i = 0; i < 2; ++i) {
        int c = tid + i * 256;       // 0..511
        int row = c >> 2, cb = c & 3;
        size_t so = (size_t)(code0 + row) * 512 + kb + cb * 16;
        uint32_t dof = row * ROWB + cb * 16;
        CP_ASYNC16(buf + SB_HI + dof, eh + so);
        CP_ASYNC16(buf + SB_LO + dof, el + so);
    }
}

__global__ void __launch_bounds__(256, 2)
k_gemm_mma(const float* __restrict__ x, const float* __restrict__ embed) {
    extern __shared__ char smem[];
    uint32_t sb;
    asm("{ .reg .u64 t; cvta.to.shared.u64 t, %1; cvt.u32.u64 %0, t; }"
        : "=r"(sb) : "l"(smem));

    const int tid = threadIdx.x;
    const int wid = tid >> 5;
    const int lane = tid & 31;
    const int wm = wid & 3;      // token strip (32)
    const int wn = wid >> 2;     // code strip (64)
    const int blockTok = blockIdx.x * 128;
    const int cc = blockIdx.y;
    const int code0 = cc * 128;

    float acc[2][8][4];
#pragma unroll
    for (int t = 0; t < 2; ++t)
#pragma unroll
        for (int j = 0; j < 8; ++j)
#pragma unroll
            for (int r = 0; r < 4; ++r) acc[t][j][r] = 0.0f;

    const uint32_t arow = (uint32_t)((wm * 32 + (lane & 15)) * ROWB + (lane >> 4) * 16);
    const int g8 = lane >> 3;
    const uint32_t brow = (uint32_t)((wn * 64 + (g8 >> 1) * 8 + (lane & 7)) * ROWB
                                     + (g8 & 1) * 16);

    load_stage(sb, 0, 0, tid, blockTok, code0);
    CP_COMMIT();

    for (int s = 0; s < 8; ++s) {
        const int b = s & 1;
        if (s < 7) {
            load_stage(sb, b ^ 1, s + 1, tid, blockTok, code0);
            CP_COMMIT();
            CP_WAIT(1);
        } else {
            CP_WAIT(0);
        }
        __syncthreads();

        const uint32_t base = sb + b * BUFB;
#pragma unroll
        for (int ks = 0; ks < 2; ++ks) {
            const uint32_t k0 = ks * 32;
            uint32_t ah[2][4], al[2][4];
#pragma unroll
            for (int t = 0; t < 2; ++t) {
                ldsm_x4(ah[t], base + SA_HI + arow + t * 16 * ROWB + k0);
                ldsm_x4(al[t], base + SA_LO + arow + t * 16 * ROWB + k0);
            }
#pragma unroll
            for (int jj = 0; jj < 4; ++jj) {
                uint32_t bh[4], bl[4];
                ldsm_x4(bh, base + SB_HI + brow + jj * 16 * ROWB + k0);
                ldsm_x4(bl, base + SB_LO + brow + jj * 16 * ROWB + k0);
#pragma unroll
                for (int t = 0; t < 2; ++t) {
                    mma_bf16(acc[t][2 * jj],     ah[t], bh);
                    mma_bf16(acc[t][2 * jj + 1], ah[t], bh + 2);
                    mma_bf16(acc[t][2 * jj],     ah[t], bl);
                    mma_bf16(acc[t][2 * jj + 1], ah[t], bl + 2);
                    mma_bf16(acc[t][2 * jj],     al[t], bh);
                    mma_bf16(acc[t][2 * jj + 1], al[t], bh + 2);
                }
            }
        }
        __syncthreads();
    }

    // ---- epilogue: score + argmax ----
    const int g = lane >> 2;       // row within 8
    const int tg = lane & 3;       // col pair selector
    float best[4];
    int bidx[4];
#pragma unroll
    for (int r = 0; r < 4; ++r) { best[r] = -CUDART_INF_F; bidx[r] = 0x7fffffff; }

#pragma unroll
    for (int t = 0; t < 2; ++t) {
#pragma unroll
        for (int j = 0; j < 8; ++j) {
            int c0 = code0 + wn * 64 + j * 8 + tg * 2;
            float e0 = __ldg(&g_enorm[c0]);
            float e1 = __ldg(&g_enorm[c0 + 1]);
            float s00 = fmaf(2.0f, acc[t][j][0], -e0);
            float s01 = fmaf(2.0f, acc[t][j][1], -e1);
            float s10 = fmaf(2.0f, acc[t][j][2], -e0);
            float s11 = fmaf(2.0f, acc[t][j][3], -e1);
            int r0 = t * 2, r1 = t * 2 + 1;
            if (s00 > best[r0]) { best[r0] = s00; bidx[r0] = c0; }
            if (s01 > best[r0]) { best[r0] = s01; bidx[r0] = c0 + 1; }
            if (s10 > best[r1]) { best[r1] = s10; bidx[r1] = c0; }
            if (s11 > best[r1]) { best[r1] = s11; bidx[r1] = c0 + 1; }
        }
    }
#pragma unroll
    for (int r = 0; r < 4; ++r) {
#pragma unroll
        for (int off = 1; off < 4; off <<= 1) {
            float os = __shfl_xor_sync(0xffffffffu, best[r], off);
            int   oi = __shfl_xor_sync(0xffffffffu, bidx[r], off);
            if (os > best[r] || (os == best[r] && oi < bidx[r])) { best[r] = os; bidx[r] = oi; }
        }
    }

    __syncthreads();  // buffers done; reuse smem as reduce scratch
    float* red_s = (float*)smem;               // [128][2]
    int*   red_i = (int*)(smem + 1024);        // [128][2]
    if (tg == 0) {
#pragma unroll
        for (int r = 0; r < 4; ++r) {
            int t = r >> 1, rh = r & 1;
            int lrow = wm * 32 + t * 16 + rh * 8 + g;
            red_s[lrow * 2 + wn] = best[r];
            red_i[lrow * 2 + wn] = bidx[r];
        }
    }
    __syncthreads();
    if (tid < 128) {
        float s0 = red_s[tid * 2], s1 = red_s[tid * 2 + 1];
        int i0 = red_i[tid * 2], i1 = red_i[tid * 2 + 1];
        float bs = s0; int bb = i0;
        if (s1 > s0) { bs = s1; bb = i1; }   // strip 0 has lower codes: tie keeps 0
        int tok = blockTok + tid;
        g_pbest[cc * N_TOK + tok] = bs;
        g_pidx[cc * N_TOK + tok] = bb;
    }
}

// ---------------- kernel 3: cross-chunk argmax reduce ----------------
__global__ void k_argmax_reduce(float* __restrict__ out_ind) {
    int tok = blockIdx.x * 256 + threadIdx.x;
    float bs = -CUDART_INF_F;
    int bi = 0x7fffffff;
#pragma unroll
    for (int cc = 0; cc < NCHUNK; ++cc) {
        float s = g_pbest[cc * N_TOK + tok];
        int i = g_pidx[cc * N_TOK + tok];
        if (s > bs) { bs = s; bi = i; }  // ascending chunks: strict > keeps lowest idx
    }
    g_idx[tok] = bi;
    out_ind[tok] = (float)bi;
}

// ---------------- kernel 4: gather quantize ----------------
__global__ void k_quant(const float* __restrict__ embed,
                        float* __restrict__ out_q) {
    int token = blockIdx.x * 8 + (threadIdx.x >> 5);
    int lane = threadIdx.x & 31;
    int idx = g_idx[token];
    const float4* er = (const float4*)(embed + (size_t)idx * DIM);
    float4* qw = (float4*)(out_q + (size_t)token * DIM);
    qw[lane] = er[lane];
    qw[lane + 32] = er[lane + 32];
}

// ---------------- kernel 5: per-code deterministic accumulation ----------------
__global__ __launch_bounds__(256)
void k_accum(const float* __restrict__ x) {
    const int c = blockIdx.x;
    const int tid = threadIdx.x;
    const int lane = tid & 31;
    const int w = tid >> 5;

    __shared__ int list[256];
    __shared__ int wcnt[8];
    __shared__ int wbase[8];
    __shared__ int s_n;

    float acc = 0.0f;
    int total = 0;

    for (int base = 0; base < N_TOK; base += 256) {
        int t = base + tid;
        bool m = (g_idx[t] == c);
        unsigned ball = __ballot_sync(0xffffffffu, m);
        if (lane == 0) wcnt[w] = __popc(ball);
        __syncthreads();
        if (tid == 0) {
            int s = 0;
#pragma unroll
            for (int i = 0; i < 8; ++i) { wbase[i] = s; s += wcnt[i]; }
            s_n = s;
        }
        __syncthreads();
        if (m) {
            int r = __popc(ball & ((1u << lane) - 1u));
            list[wbase[w] + r] = t;
        }
        __syncthreads();
        int n = s_n;
        for (int j = 0; j < n; ++j)
            acc += x[(size_t)list[j] * DIM + tid];
        total += n;
        __syncthreads();
    }

    g_esum[(size_t)c * DIM + tid] = acc;
    if (tid == 0) g_counts[c] = (float)total;
}

// ---------------- kernel 6a: cs_new + Laplace smoothing reciprocal ----------------
__global__ void k_finA(const float* __restrict__ cluster_size,
                       float* __restrict__ out_cs) {
    __shared__ float red[NCODE];
    int c = threadIdx.x;
    float csn = DECAY * cluster_size[c] + ONE_M_DECAY * g_counts[c];
    out_cs[c] = csn;
    red[c] = csn;
    __syncthreads();
#pragma unroll
    for (int s = 512; s > 0; s >>= 1) {
        if (c < s) red[c] += red[c + s];
        __syncthreads();
    }
    float n = red[0];
    float denom = (csn + EPS) / (n + (float)NCODE * EPS) * n;
    g_inv[c] = 1.0f / denom;
}

// ---------------- kernel 6b: embed_norm ----------------
__global__ void k_finB(const float* __restrict__ embed_avg,
                       float* __restrict__ out_norm) {
    int i = blockIdx.x * blockDim.x + threadIdx.x;
    if (i < NCODE * DIM) {
        float ea = DECAY * embed_avg[i] + ONE_M_DECAY * g_esum[i];
        out_norm[i] = ea * g_inv[i >> 8];
    }
}

// ---------------- launch ----------------
extern "C" void kernel_launch(void* const* d_in, const int* in_sizes, int n_in,
                              void* d_out, int out_size) {
    const float* x = (const float*)d_in[0];
    const float* embed = (const float*)d_in[1];
    const float* embed_avg = (const float*)d_in[2];
    const float* cluster_size = (const float*)d_in[3];
    float* out = (float*)d_out;

    float* out_q    = out + OFF_Q;
    float* out_ind  = out + OFF_IND;
    float* out_norm = out + OFF_NORM;
    float* out_cs   = out + OFF_CS;

    cudaFuncSetAttribute(k_gemm_mma,
                         cudaFuncAttributeMaxDynamicSharedMemorySize,
                         DSMEM2);

    k_prep<<<8448, 256>>>(x, embed);
    k_enorm<<<NCODE / 4, 128>>>(embed);
    dim3 g(N_TOK / 128, NCHUNK);
    k_gemm_mma<<<g, 256, DSMEM2>>>(x, embed);
    k_argmax_reduce<<<N_TOK / 256, 256>>>(out_ind);
    k_quant<<<N_TOK / 8, 256>>>(embed, out_q);
    k_accum<<<NCODE, 256>>>(x);
    k_finA<<<1, NCODE>>>(cluster_size, out_cs);
    k_finB<<<(NCODE * DIM + 255) / 256, 256>>>(embed_avg, out_norm);
}